// round 6
// baseline (speedup 1.0000x reference)
#include <cuda_runtime.h>
#include <cuda_bf16.h>
#include <math.h>
#include <stdint.h>

#define N_  16
#define C_  128
#define S_  16384
#define K_  64
#define TS  128
#define TILES 4
#define SGROUPS (S_ / (TS * TILES))   // 32
#define NBLK (N_ * SGROUPS)           // 512
#define NTH 256
#define LDX 136   // bf16 row stride x tiles [s][c] (col 128 = ||x|| hi/lo)
#define LDW 136
#define LDT 136
#define PSTRIDE 8256                  // 8192 vacc + 64 asum per block partial

__device__ float g_part[NBLK * PSTRIDE];

// ---------------------------------------------------------------------------
__device__ __forceinline__ uint32_t s2u(const void* p) {
    uint32_t a;
    asm("{ .reg .u64 t; cvta.to.shared.u64 t, %1; cvt.u32.u64 %0, t; }"
        : "=r"(a) : "l"(p));
    return a;
}
__device__ __forceinline__ void ldsm4(uint32_t* r, uint32_t addr) {
    asm volatile("ldmatrix.sync.aligned.m8n8.x4.shared.b16 {%0,%1,%2,%3}, [%4];"
                 : "=r"(r[0]), "=r"(r[1]), "=r"(r[2]), "=r"(r[3]) : "r"(addr));
}
__device__ __forceinline__ void ldsm2t(uint32_t& r0, uint32_t& r1, uint32_t addr) {
    asm volatile("ldmatrix.sync.aligned.m8n8.x2.trans.shared.b16 {%0,%1}, [%2];"
                 : "=r"(r0), "=r"(r1) : "r"(addr));
}
__device__ __forceinline__ void mma_bf16(float* d, const uint32_t* a,
                                         uint32_t b0, uint32_t b1) {
    asm volatile("mma.sync.aligned.m16n8k16.row.col.f32.bf16.bf16.f32 "
                 "{%0,%1,%2,%3}, {%4,%5,%6,%7}, {%8,%9}, {%0,%1,%2,%3};"
                 : "+f"(d[0]), "+f"(d[1]), "+f"(d[2]), "+f"(d[3])
                 : "r"(a[0]), "r"(a[1]), "r"(a[2]), "r"(a[3]), "r"(b0), "r"(b1));
}

// ---------------------------------------------------------------------------
// smem byte offsets
#define OFF_XH   0
#define OFF_XL   34816
#define OFF_WH   69632
#define OFF_WL   87040
#define OFF_SH   104448
#define OFF_SL   121856
#define OFF_BB   139264
#define OFF_PN   139520
#define SMEM_TOT 140544

__global__ __launch_bounds__(NTH, 1)
void nv_main_kernel(const float* __restrict__ x,
                    const float* __restrict__ fc_w,
                    const float* __restrict__ fc_b) {
    extern __shared__ char smem[];
    __nv_bfloat16* XH  = (__nv_bfloat16*)(smem + OFF_XH);
    __nv_bfloat16* XL  = (__nv_bfloat16*)(smem + OFF_XL);
    __nv_bfloat16* WH  = (__nv_bfloat16*)(smem + OFF_WH);
    __nv_bfloat16* WL  = (__nv_bfloat16*)(smem + OFF_WL);
    __nv_bfloat16* SHm = (__nv_bfloat16*)(smem + OFF_SH);
    __nv_bfloat16* SLm = (__nv_bfloat16*)(smem + OFF_SL);
    float* BB = (float*)(smem + OFF_BB);
    float* PN = (float*)(smem + OFF_PN);

    const uint32_t XHu = s2u(XH), XLu = s2u(XL), WHu = s2u(WH), WLu = s2u(WL);
    const uint32_t SHu = s2u(SHm), SLu = s2u(SLm);

    const int n   = blockIdx.x >> 5;
    const int g   = blockIdx.x & (SGROUPS - 1);
    const int tid = threadIdx.x;
    const int l   = tid & 31;
    const int w   = tid >> 5;
    const int sl  = tid & 127;     // position in tile (load/convert)
    const int hh  = tid >> 7;      // channel half

    // ---- load fc_w hi/lo + bias (once per block) ----
    for (int i = tid; i < K_ * C_; i += NTH) {
        int k = i >> 7, c = i & 127;
        float v = fc_w[i];
        __nv_bfloat16 hi = __float2bfloat16(v);
        WH[k * LDW + c] = hi;
        WL[k * LDW + c] = __float2bfloat16(v - __bfloat162float(hi));
    }
    if (tid < K_) BB[tid] = fc_b[tid];
    __syncthreads();

    const int cst = (l & 3) * 2;
    float bias_r[8][2];
    #pragma unroll
    for (int j = 0; j < 8; j++) {
        bias_r[j][0] = BB[j * 8 + cst];
        bias_r[j][1] = BB[j * 8 + cst + 1];
    }

    // persistent GEMM2 accumulators
    const int m0b = (w & 3) * 16;
    const int nb  = (w >> 2) * 64;
    float vacc[8][4];
    #pragma unroll
    for (int j = 0; j < 8; j++)
        #pragma unroll
        for (int q = 0; q < 4; q++) vacc[j][q] = 0.0f;
    float vacc8[4] = {0.f, 0.f, 0.f, 0.f};   // norm-column (a_sum)

    #pragma unroll 1
    for (int t = 0; t < TILES; t++) {
        const int s0 = g * (TS * TILES) + t * TS;
        const float* xg = x + (size_t)n * C_ * S_ + s0;
        __syncthreads();                         // A: prev tile consumers done

        // ---- pass 1 (only pass): load raw x, hi/lo split, ss partial ----
        float ss = 0.0f;
        #pragma unroll 8
        for (int c = hh * 64; c < hh * 64 + 64; c += 2) {
            float v0 = xg[(size_t)c * S_ + sl];
            float v1 = xg[(size_t)(c + 1) * S_ + sl];
            ss = fmaf(v0, v0, ss); ss = fmaf(v1, v1, ss);
            __nv_bfloat16 h0 = __float2bfloat16(v0);
            __nv_bfloat16 h1 = __float2bfloat16(v1);
            __nv_bfloat162 hp; hp.x = h0; hp.y = h1;
            __nv_bfloat162 lp;
            lp.x = __float2bfloat16(v0 - __bfloat162float(h0));
            lp.y = __float2bfloat16(v1 - __bfloat162float(h1));
            *(__nv_bfloat162*)&XH[sl * LDX + c] = hp;
            *(__nv_bfloat162*)&XL[sl * LDX + c] = lp;
        }
        PN[sl * 2 + hh] = ss;
        __syncthreads();                         // S1: XH/XL + PN ready

        // norm column (c=128): ||x_s|| hi/lo, so soft' @ normcol = a_sum
        if (hh == 0) {
            float nrm = fmaxf(sqrtf(PN[sl * 2] + PN[sl * 2 + 1]), 1e-12f);
            __nv_bfloat16 h = __float2bfloat16(nrm);
            XH[sl * LDX + 128] = h;
            XL[sl * LDX + 128] = __float2bfloat16(nrm - __bfloat162float(h));
        }

        // ---- GEMM1 on RAW x: acc = xraw @ w^T  (3-term bf16 hi/lo) ----
        float lacc[8][4];
        #pragma unroll
        for (int j = 0; j < 8; j++)
            #pragma unroll
            for (int q = 0; q < 4; q++) lacc[j][q] = 0.0f;
        {
            const int m0 = w * 16;
            uint32_t aoffA = (uint32_t)(((m0 + (l & 15)) * LDX + ((l >> 4) << 3)) * 2);
            uint32_t boffB = (uint32_t)(((((l >> 4) << 3) + (l & 7)) * LDW
                                        + (((l >> 3) & 1) << 3)) * 2);
            #pragma unroll 1
            for (int kc = 0; kc < 8; kc++) {
                uint32_t axh[4], axl[4];
                ldsm4(axh, XHu + aoffA + kc * 32);
                ldsm4(axl, XLu + aoffA + kc * 32);
                #pragma unroll
                for (int j = 0; j < 4; j++) {
                    uint32_t bwh[4], bwl[4];
                    uint32_t bo = boffB + kc * 32 + j * 16 * LDW * 2;
                    ldsm4(bwh, WHu + bo);
                    ldsm4(bwl, WLu + bo);
                    mma_bf16(lacc[2*j],   axh, bwh[0], bwh[1]);
                    mma_bf16(lacc[2*j+1], axh, bwh[2], bwh[3]);
                    mma_bf16(lacc[2*j],   axl, bwh[0], bwh[1]);
                    mma_bf16(lacc[2*j+1], axl, bwh[2], bwh[3]);
                    mma_bf16(lacc[2*j],   axh, bwl[0], bwl[1]);
                    mma_bf16(lacc[2*j+1], axh, bwl[2], bwl[3]);
                }
            }
        }

        // ---- post-scale + register softmax + fold scale into soft ----
        {
            const int m0 = w * 16;
            const int r0 = m0 + (l >> 2);
            float sc0 = 1.0f / fmaxf(sqrtf(PN[2*r0] + PN[2*r0+1]), 1e-12f);
            float sc1 = 1.0f / fmaxf(sqrtf(PN[2*(r0+8)] + PN[2*(r0+8)+1]), 1e-12f);

            float mx0 = -INFINITY, mx1 = -INFINITY;
            #pragma unroll
            for (int j = 0; j < 8; j++) {
                lacc[j][0] = fmaf(lacc[j][0], sc0, bias_r[j][0]);
                lacc[j][1] = fmaf(lacc[j][1], sc0, bias_r[j][1]);
                lacc[j][2] = fmaf(lacc[j][2], sc1, bias_r[j][0]);
                lacc[j][3] = fmaf(lacc[j][3], sc1, bias_r[j][1]);
                mx0 = fmaxf(mx0, fmaxf(lacc[j][0], lacc[j][1]));
                mx1 = fmaxf(mx1, fmaxf(lacc[j][2], lacc[j][3]));
            }
            mx0 = fmaxf(mx0, __shfl_xor_sync(0xffffffffu, mx0, 1));
            mx0 = fmaxf(mx0, __shfl_xor_sync(0xffffffffu, mx0, 2));
            mx1 = fmaxf(mx1, __shfl_xor_sync(0xffffffffu, mx1, 1));
            mx1 = fmaxf(mx1, __shfl_xor_sync(0xffffffffu, mx1, 2));
            float se0 = 0.0f, se1 = 0.0f;
            #pragma unroll
            for (int j = 0; j < 8; j++) {
                float e;
                e = __expf(lacc[j][0] - mx0); lacc[j][0] = e; se0 += e;
                e = __expf(lacc[j][1] - mx0); lacc[j][1] = e; se0 += e;
                e = __expf(lacc[j][2] - mx1); lacc[j][2] = e; se1 += e;
                e = __expf(lacc[j][3] - mx1); lacc[j][3] = e; se1 += e;
            }
            se0 += __shfl_xor_sync(0xffffffffu, se0, 1);
            se0 += __shfl_xor_sync(0xffffffffu, se0, 2);
            se1 += __shfl_xor_sync(0xffffffffu, se1, 1);
            se1 += __shfl_xor_sync(0xffffffffu, se1, 2);
            float inv0 = sc0 / se0, inv1 = sc1 / se1;   // scale folded in

            #pragma unroll
            for (int j = 0; j < 8; j++) {
                int k0 = j * 8 + cst;
                float v00 = lacc[j][0] * inv0, v01 = lacc[j][1] * inv0;
                float v10 = lacc[j][2] * inv1, v11 = lacc[j][3] * inv1;
                __nv_bfloat16 h;
                h = __float2bfloat16(v00);
                SHm[k0 * LDT + r0] = h;
                SLm[k0 * LDT + r0] = __float2bfloat16(v00 - __bfloat162float(h));
                h = __float2bfloat16(v01);
                SHm[(k0 + 1) * LDT + r0] = h;
                SLm[(k0 + 1) * LDT + r0] = __float2bfloat16(v01 - __bfloat162float(h));
                h = __float2bfloat16(v10);
                SHm[k0 * LDT + r0 + 8] = h;
                SLm[k0 * LDT + r0 + 8] = __float2bfloat16(v10 - __bfloat162float(h));
                h = __float2bfloat16(v11);
                SHm[(k0 + 1) * LDT + r0 + 8] = h;
                SLm[(k0 + 1) * LDT + r0 + 8] = __float2bfloat16(v11 - __bfloat162float(h));
            }
        }
        __syncthreads();                         // S2: soft' + norm col ready

        // ---- GEMM2: vlad += soft'T @ xraw (3-term) + norm-col a_sum ----
        #pragma unroll 1
        for (int ks = 0; ks < 8; ks++) {
            int sb = ks * 16;
            uint32_t aoff = (uint32_t)(((m0b + (l & 15)) * LDT + sb
                                       + ((l >> 4) << 3)) * 2);
            uint32_t ash[4], asl[4];
            ldsm4(ash, SHu + aoff);
            ldsm4(asl, SLu + aoff);
            uint32_t boff = (uint32_t)(((sb + (l & 15)) * LDX) * 2);
            #pragma unroll
            for (int j = 0; j < 8; j++) {
                int n0 = nb + j * 8;
                uint32_t bxh0, bxh1, bxl0, bxl1;
                ldsm2t(bxh0, bxh1, XHu + boff + n0 * 2);
                ldsm2t(bxl0, bxl1, XLu + boff + n0 * 2);
                mma_bf16(vacc[j], ash, bxh0, bxh1);
                mma_bf16(vacc[j], asl, bxh0, bxh1);
                mma_bf16(vacc[j], ash, bxl0, bxl1);
            }
            if (nb == 64) {   // norm column at c=128 -> a_sum
                uint32_t bxh0, bxh1, bxl0, bxl1;
                ldsm2t(bxh0, bxh1, XHu + boff + 128 * 2);
                ldsm2t(bxl0, bxl1, XLu + boff + 128 * 2);
                mma_bf16(vacc8, ash, bxh0, bxh1);
                mma_bf16(vacc8, asl, bxh0, bxh1);
                mma_bf16(vacc8, ash, bxl0, bxl1);
            }
        }
    }

    // ---- write per-block partial (no atomics) ----
    float* vdst = g_part + (size_t)blockIdx.x * PSTRIDE;
    {
        int r0 = m0b + (l >> 2);
        #pragma unroll
        for (int j = 0; j < 8; j++) {
            int c = nb + j * 8 + cst;
            vdst[r0 * C_ + c]           = vacc[j][0];
            vdst[r0 * C_ + c + 1]       = vacc[j][1];
            vdst[(r0 + 8) * C_ + c]     = vacc[j][2];
            vdst[(r0 + 8) * C_ + c + 1] = vacc[j][3];
        }
        if (nb == 64 && (l & 3) == 0) {
            vdst[8192 + r0]     = vacc8[0];
            vdst[8192 + r0 + 8] = vacc8[2];
        }
    }
}

// ---------------------------------------------------------------------------
// Reduce 32 partials per n + subtract a_sum*centroids + intra/global norm.
__global__ __launch_bounds__(256)
void nv_finalize_kernel(const float* __restrict__ centroids,
                        float* __restrict__ out) {
    __shared__ float vsh[K_ * C_];
    __shared__ float ash[K_];
    __shared__ float wsum[8];

    const int n   = blockIdx.x;
    const int tid = threadIdx.x;
    const float* pbase = g_part + (size_t)n * SGROUPS * PSTRIDE;

    // reduce vacc partials
    for (int e = tid; e < K_ * C_; e += 256) {
        float s = 0.0f;
        #pragma unroll 8
        for (int p = 0; p < SGROUPS; p++)
            s += pbase[(size_t)p * PSTRIDE + e];
        vsh[e] = s;
    }
    if (tid < K_) {
        float s = 0.0f;
        #pragma unroll 8
        for (int p = 0; p < SGROUPS; p++)
            s += pbase[(size_t)p * PSTRIDE + 8192 + tid];
        ash[tid] = s;
    }
    __syncthreads();

    // per-(k) intra-normalization: thread group of 4 per k, 32 channels each
    const int k  = tid >> 2;
    const int cb = (tid & 3) * 32;
    const float ak = ash[k];

    float ssk = 0.0f;
    #pragma unroll 8
    for (int c = 0; c < 32; c++) {
        int idx = k * C_ + cb + c;
        float v = vsh[idx] - ak * centroids[idx];
        vsh[idx] = v;
        ssk = fmaf(v, v, ssk);
    }
    ssk += __shfl_xor_sync(0xffffffffu, ssk, 1);
    ssk += __shfl_xor_sync(0xffffffffu, ssk, 2);
    float rinv = 1.0f / fmaxf(sqrtf(ssk), 1e-12f);

    float tot = 0.0f;
    #pragma unroll 8
    for (int c = 0; c < 32; c++) {
        int idx = k * C_ + cb + c;
        float tv = vsh[idx] * rinv;
        vsh[idx] = tv;
        tot = fmaf(tv, tv, tot);
    }
    #pragma unroll
    for (int off = 16; off > 0; off >>= 1)
        tot += __shfl_xor_sync(0xffffffffu, tot, off);
    if ((tid & 31) == 0) wsum[tid >> 5] = tot;
    __syncthreads();
    float total = 0.0f;
    #pragma unroll
    for (int i = 0; i < 8; i++) total += wsum[i];
    float ginv = 1.0f / fmaxf(sqrtf(total), 1e-12f);

    float* od = out + (size_t)n * K_ * C_;
    for (int i = tid; i < K_ * C_; i += 256)
        od[i] = vsh[i] * ginv;
}

// ---------------------------------------------------------------------------
extern "C" void kernel_launch(void* const* d_in, const int* in_sizes, int n_in,
                              void* d_out, int out_size) {
    const float* x         = (const float*)d_in[0];
    const float* fc_w      = (const float*)d_in[1];
    const float* fc_b      = (const float*)d_in[2];
    const float* centroids = (const float*)d_in[3];
    float* out = (float*)d_out;

    cudaFuncSetAttribute(nv_main_kernel,
                         cudaFuncAttributeMaxDynamicSharedMemorySize,
                         SMEM_TOT);

    nv_main_kernel<<<NBLK, NTH, SMEM_TOT>>>(x, fc_w, fc_b);
    nv_finalize_kernel<<<N_, 256>>>(centroids, out);
}

// round 7
// speedup vs baseline: 1.3409x; 1.3409x over previous
#include <cuda_runtime.h>
#include <cuda_bf16.h>
#include <math.h>
#include <stdint.h>

#define N_  16
#define C_  128
#define S_  16384
#define K_  64
#define TS  128
#define TILES 4
#define SGROUPS (S_ / (TS * TILES))   // 32
#define NBLK (N_ * SGROUPS)           // 512
#define NTH 256
#define LDX 136   // bf16 row stride x tiles [s][c] (col 128 = ||x|| hi/lo)
#define LDW 136
#define LDT 136
#define PSTRIDE 8256                  // 8192 vacc + 64 asum per block partial

__device__ float g_part[NBLK * PSTRIDE];
__device__ float g_red[N_ * PSTRIDE];

// ---------------------------------------------------------------------------
__device__ __forceinline__ uint32_t s2u(const void* p) {
    uint32_t a;
    asm("{ .reg .u64 t; cvta.to.shared.u64 t, %1; cvt.u32.u64 %0, t; }"
        : "=r"(a) : "l"(p));
    return a;
}
__device__ __forceinline__ void ldsm4(uint32_t* r, uint32_t addr) {
    asm volatile("ldmatrix.sync.aligned.m8n8.x4.shared.b16 {%0,%1,%2,%3}, [%4];"
                 : "=r"(r[0]), "=r"(r[1]), "=r"(r[2]), "=r"(r[3]) : "r"(addr));
}
__device__ __forceinline__ void ldsm2t(uint32_t& r0, uint32_t& r1, uint32_t addr) {
    asm volatile("ldmatrix.sync.aligned.m8n8.x2.trans.shared.b16 {%0,%1}, [%2];"
                 : "=r"(r0), "=r"(r1) : "r"(addr));
}
__device__ __forceinline__ void mma_bf16(float* d, const uint32_t* a,
                                         uint32_t b0, uint32_t b1) {
    asm volatile("mma.sync.aligned.m16n8k16.row.col.f32.bf16.bf16.f32 "
                 "{%0,%1,%2,%3}, {%4,%5,%6,%7}, {%8,%9}, {%0,%1,%2,%3};"
                 : "+f"(d[0]), "+f"(d[1]), "+f"(d[2]), "+f"(d[3])
                 : "r"(a[0]), "r"(a[1]), "r"(a[2]), "r"(a[3]), "r"(b0), "r"(b1));
}

// ---------------------------------------------------------------------------
// smem byte offsets
#define OFF_XH   0
#define OFF_XL   34816
#define OFF_WH   69632
#define OFF_WL   87040
#define OFF_SH   104448
#define OFF_SL   121856
#define OFF_BB   139264
#define OFF_PN   139520
#define SMEM_TOT 140544

__global__ __launch_bounds__(NTH, 1)
void nv_main_kernel(const float* __restrict__ x,
                    const float* __restrict__ fc_w,
                    const float* __restrict__ fc_b) {
    extern __shared__ char smem[];
    __nv_bfloat16* XH  = (__nv_bfloat16*)(smem + OFF_XH);
    __nv_bfloat16* XL  = (__nv_bfloat16*)(smem + OFF_XL);
    __nv_bfloat16* WH  = (__nv_bfloat16*)(smem + OFF_WH);
    __nv_bfloat16* WL  = (__nv_bfloat16*)(smem + OFF_WL);
    __nv_bfloat16* SHm = (__nv_bfloat16*)(smem + OFF_SH);
    __nv_bfloat16* SLm = (__nv_bfloat16*)(smem + OFF_SL);
    float* BB = (float*)(smem + OFF_BB);
    float* PN = (float*)(smem + OFF_PN);

    const uint32_t XHu = s2u(XH), XLu = s2u(XL), WHu = s2u(WH), WLu = s2u(WL);
    const uint32_t SHu = s2u(SHm), SLu = s2u(SLm);

    const int n   = blockIdx.x >> 5;
    const int g   = blockIdx.x & (SGROUPS - 1);
    const int tid = threadIdx.x;
    const int l   = tid & 31;
    const int w   = tid >> 5;
    const int sl  = tid & 127;     // position in tile (load/convert)
    const int hh  = tid >> 7;      // channel half

    // ---- load fc_w hi/lo + bias (once per block) ----
    for (int i = tid; i < K_ * C_; i += NTH) {
        int k = i >> 7, c = i & 127;
        float v = fc_w[i];
        __nv_bfloat16 hi = __float2bfloat16(v);
        WH[k * LDW + c] = hi;
        WL[k * LDW + c] = __float2bfloat16(v - __bfloat162float(hi));
    }
    if (tid < K_) BB[tid] = fc_b[tid];
    __syncthreads();

    const int cst = (l & 3) * 2;
    float bias_r[8][2];
    #pragma unroll
    for (int j = 0; j < 8; j++) {
        bias_r[j][0] = BB[j * 8 + cst];
        bias_r[j][1] = BB[j * 8 + cst + 1];
    }

    // persistent GEMM2 accumulators
    const int m0b = (w & 3) * 16;
    const int nb  = (w >> 2) * 64;
    float vacc[8][4];
    #pragma unroll
    for (int j = 0; j < 8; j++)
        #pragma unroll
        for (int q = 0; q < 4; q++) vacc[j][q] = 0.0f;
    float vacc8[4] = {0.f, 0.f, 0.f, 0.f};   // norm-column (a_sum)

    #pragma unroll 1
    for (int t = 0; t < TILES; t++) {
        const int s0 = g * (TS * TILES) + t * TS;
        const float* xg = x + (size_t)n * C_ * S_ + s0;
        __syncthreads();                         // A: prev tile consumers done

        // ---- single pass: load raw x, hi/lo split, ss partial ----
        float ss = 0.0f;
        #pragma unroll 8
        for (int c = hh * 64; c < hh * 64 + 64; c += 2) {
            float v0 = xg[(size_t)c * S_ + sl];
            float v1 = xg[(size_t)(c + 1) * S_ + sl];
            ss = fmaf(v0, v0, ss); ss = fmaf(v1, v1, ss);
            __nv_bfloat16 h0 = __float2bfloat16(v0);
            __nv_bfloat16 h1 = __float2bfloat16(v1);
            __nv_bfloat162 hp; hp.x = h0; hp.y = h1;
            __nv_bfloat162 lp;
            lp.x = __float2bfloat16(v0 - __bfloat162float(h0));
            lp.y = __float2bfloat16(v1 - __bfloat162float(h1));
            *(__nv_bfloat162*)&XH[sl * LDX + c] = hp;
            *(__nv_bfloat162*)&XL[sl * LDX + c] = lp;
        }
        PN[sl * 2 + hh] = ss;
        __syncthreads();                         // S1: XH/XL + PN ready

        // norm column (c=128): ||x_s|| hi/lo, so soft' @ normcol = a_sum
        if (hh == 0) {
            float nrm = fmaxf(sqrtf(PN[sl * 2] + PN[sl * 2 + 1]), 1e-12f);
            __nv_bfloat16 h = __float2bfloat16(nrm);
            XH[sl * LDX + 128] = h;
            XL[sl * LDX + 128] = __float2bfloat16(nrm - __bfloat162float(h));
        }

        // ---- GEMM1 on RAW x: acc = xraw @ w^T  (3-term bf16 hi/lo) ----
        float lacc[8][4];
        #pragma unroll
        for (int j = 0; j < 8; j++)
            #pragma unroll
            for (int q = 0; q < 4; q++) lacc[j][q] = 0.0f;
        {
            const int m0 = w * 16;
            uint32_t aoffA = (uint32_t)(((m0 + (l & 15)) * LDX + ((l >> 4) << 3)) * 2);
            uint32_t boffB = (uint32_t)(((((l >> 4) << 3) + (l & 7)) * LDW
                                        + (((l >> 3) & 1) << 3)) * 2);
            #pragma unroll 1
            for (int kc = 0; kc < 8; kc++) {
                uint32_t axh[4], axl[4];
                ldsm4(axh, XHu + aoffA + kc * 32);
                ldsm4(axl, XLu + aoffA + kc * 32);
                #pragma unroll
                for (int j = 0; j < 4; j++) {
                    uint32_t bwh[4], bwl[4];
                    uint32_t bo = boffB + kc * 32 + j * 16 * LDW * 2;
                    ldsm4(bwh, WHu + bo);
                    ldsm4(bwl, WLu + bo);
                    mma_bf16(lacc[2*j],   axh, bwh[0], bwh[1]);
                    mma_bf16(lacc[2*j+1], axh, bwh[2], bwh[3]);
                    mma_bf16(lacc[2*j],   axl, bwh[0], bwh[1]);
                    mma_bf16(lacc[2*j+1], axl, bwh[2], bwh[3]);
                    mma_bf16(lacc[2*j],   axh, bwl[0], bwl[1]);
                    mma_bf16(lacc[2*j+1], axh, bwl[2], bwl[3]);
                }
            }
        }

        // ---- post-scale + register softmax + fold scale into soft ----
        {
            const int m0 = w * 16;
            const int r0 = m0 + (l >> 2);
            float sc0 = 1.0f / fmaxf(sqrtf(PN[2*r0] + PN[2*r0+1]), 1e-12f);
            float sc1 = 1.0f / fmaxf(sqrtf(PN[2*(r0+8)] + PN[2*(r0+8)+1]), 1e-12f);

            float mx0 = -INFINITY, mx1 = -INFINITY;
            #pragma unroll
            for (int j = 0; j < 8; j++) {
                lacc[j][0] = fmaf(lacc[j][0], sc0, bias_r[j][0]);
                lacc[j][1] = fmaf(lacc[j][1], sc0, bias_r[j][1]);
                lacc[j][2] = fmaf(lacc[j][2], sc1, bias_r[j][0]);
                lacc[j][3] = fmaf(lacc[j][3], sc1, bias_r[j][1]);
                mx0 = fmaxf(mx0, fmaxf(lacc[j][0], lacc[j][1]));
                mx1 = fmaxf(mx1, fmaxf(lacc[j][2], lacc[j][3]));
            }
            mx0 = fmaxf(mx0, __shfl_xor_sync(0xffffffffu, mx0, 1));
            mx0 = fmaxf(mx0, __shfl_xor_sync(0xffffffffu, mx0, 2));
            mx1 = fmaxf(mx1, __shfl_xor_sync(0xffffffffu, mx1, 1));
            mx1 = fmaxf(mx1, __shfl_xor_sync(0xffffffffu, mx1, 2));
            float se0 = 0.0f, se1 = 0.0f;
            #pragma unroll
            for (int j = 0; j < 8; j++) {
                float e;
                e = __expf(lacc[j][0] - mx0); lacc[j][0] = e; se0 += e;
                e = __expf(lacc[j][1] - mx0); lacc[j][1] = e; se0 += e;
                e = __expf(lacc[j][2] - mx1); lacc[j][2] = e; se1 += e;
                e = __expf(lacc[j][3] - mx1); lacc[j][3] = e; se1 += e;
            }
            se0 += __shfl_xor_sync(0xffffffffu, se0, 1);
            se0 += __shfl_xor_sync(0xffffffffu, se0, 2);
            se1 += __shfl_xor_sync(0xffffffffu, se1, 1);
            se1 += __shfl_xor_sync(0xffffffffu, se1, 2);
            float inv0 = sc0 / se0, inv1 = sc1 / se1;   // scale folded in

            #pragma unroll
            for (int j = 0; j < 8; j++) {
                int k0 = j * 8 + cst;
                float v00 = lacc[j][0] * inv0, v01 = lacc[j][1] * inv0;
                float v10 = lacc[j][2] * inv1, v11 = lacc[j][3] * inv1;
                __nv_bfloat16 h;
                h = __float2bfloat16(v00);
                SHm[k0 * LDT + r0] = h;
                SLm[k0 * LDT + r0] = __float2bfloat16(v00 - __bfloat162float(h));
                h = __float2bfloat16(v01);
                SHm[(k0 + 1) * LDT + r0] = h;
                SLm[(k0 + 1) * LDT + r0] = __float2bfloat16(v01 - __bfloat162float(h));
                h = __float2bfloat16(v10);
                SHm[k0 * LDT + r0 + 8] = h;
                SLm[k0 * LDT + r0 + 8] = __float2bfloat16(v10 - __bfloat162float(h));
                h = __float2bfloat16(v11);
                SHm[(k0 + 1) * LDT + r0 + 8] = h;
                SLm[(k0 + 1) * LDT + r0 + 8] = __float2bfloat16(v11 - __bfloat162float(h));
            }
        }
        __syncthreads();                         // S2: soft' + norm col ready

        // ---- GEMM2: vlad += soft'T @ xraw (3-term) + norm-col a_sum ----
        #pragma unroll 1
        for (int ks = 0; ks < 8; ks++) {
            int sb = ks * 16;
            uint32_t aoff = (uint32_t)(((m0b + (l & 15)) * LDT + sb
                                       + ((l >> 4) << 3)) * 2);
            uint32_t ash[4], asl[4];
            ldsm4(ash, SHu + aoff);
            ldsm4(asl, SLu + aoff);
            uint32_t boff = (uint32_t)(((sb + (l & 15)) * LDX) * 2);
            #pragma unroll
            for (int j = 0; j < 8; j++) {
                int n0 = nb + j * 8;
                uint32_t bxh0, bxh1, bxl0, bxl1;
                ldsm2t(bxh0, bxh1, XHu + boff + n0 * 2);
                ldsm2t(bxl0, bxl1, XLu + boff + n0 * 2);
                mma_bf16(vacc[j], ash, bxh0, bxh1);
                mma_bf16(vacc[j], asl, bxh0, bxh1);
                mma_bf16(vacc[j], ash, bxl0, bxl1);
            }
            if (nb == 64) {   // norm column at c=128 -> a_sum
                uint32_t bxh0, bxh1, bxl0, bxl1;
                ldsm2t(bxh0, bxh1, XHu + boff + 128 * 2);
                ldsm2t(bxl0, bxl1, XLu + boff + 128 * 2);
                mma_bf16(vacc8, ash, bxh0, bxh1);
                mma_bf16(vacc8, asl, bxh0, bxh1);
                mma_bf16(vacc8, ash, bxl0, bxl1);
            }
        }
    }

    // ---- write per-block partial (no atomics) ----
    float* vdst = g_part + (size_t)blockIdx.x * PSTRIDE;
    {
        int r0 = m0b + (l >> 2);
        #pragma unroll
        for (int j = 0; j < 8; j++) {
            int c = nb + j * 8 + cst;
            vdst[r0 * C_ + c]           = vacc[j][0];
            vdst[r0 * C_ + c + 1]       = vacc[j][1];
            vdst[(r0 + 8) * C_ + c]     = vacc[j][2];
            vdst[(r0 + 8) * C_ + c + 1] = vacc[j][3];
        }
        if (nb == 64 && (l & 3) == 0) {
            vdst[8192 + r0]     = vacc8[0];
            vdst[8192 + r0 + 8] = vacc8[2];
        }
    }
}

// ---------------------------------------------------------------------------
// Wide parallel reduction: 512 partials -> 16. Each thread owns one float4
// of one n's output, sums 32 partials with independent unrolled loads.
#define REDV (PSTRIDE / 4)            // 2064 float4 per n
__global__ __launch_bounds__(256)
void nv_reduce_kernel() {
    int idx = blockIdx.x * 256 + threadIdx.x;
    if (idx >= N_ * REDV) return;
    int n  = idx / REDV;
    int e4 = idx - n * REDV;
    const float4* pb = (const float4*)(g_part + (size_t)n * SGROUPS * PSTRIDE)
                       + e4;
    float4 s = make_float4(0.f, 0.f, 0.f, 0.f);
    #pragma unroll 8
    for (int p = 0; p < SGROUPS; p++) {
        float4 v = pb[(size_t)p * (PSTRIDE / 4)];
        s.x += v.x; s.y += v.y; s.z += v.z; s.w += v.w;
    }
    ((float4*)(g_red + (size_t)n * PSTRIDE))[e4] = s;
}

// ---------------------------------------------------------------------------
// Finalize: subtract a_sum*centroids + intra/global norm from reduced buffer.
__global__ __launch_bounds__(256)
void nv_finalize_kernel(const float* __restrict__ centroids,
                        float* __restrict__ out) {
    __shared__ float vsh[K_ * C_];
    __shared__ float ash[K_];
    __shared__ float wsum[8];

    const int n   = blockIdx.x;
    const int tid = threadIdx.x;
    const float* rb = g_red + (size_t)n * PSTRIDE;

    for (int e = tid * 4; e < K_ * C_; e += 256 * 4)
        *(float4*)&vsh[e] = *(const float4*)&rb[e];
    if (tid < K_) ash[tid] = rb[8192 + tid];
    __syncthreads();

    const int k  = tid >> 2;
    const int cb = (tid & 3) * 32;
    const float ak = ash[k];

    float ssk = 0.0f;
    #pragma unroll 8
    for (int c = 0; c < 32; c++) {
        int idx = k * C_ + cb + c;
        float v = vsh[idx] - ak * centroids[idx];
        vsh[idx] = v;
        ssk = fmaf(v, v, ssk);
    }
    ssk += __shfl_xor_sync(0xffffffffu, ssk, 1);
    ssk += __shfl_xor_sync(0xffffffffu, ssk, 2);
    float rinv = 1.0f / fmaxf(sqrtf(ssk), 1e-12f);

    float tot = 0.0f;
    #pragma unroll 8
    for (int c = 0; c < 32; c++) {
        int idx = k * C_ + cb + c;
        float tv = vsh[idx] * rinv;
        vsh[idx] = tv;
        tot = fmaf(tv, tv, tot);
    }
    #pragma unroll
    for (int off = 16; off > 0; off >>= 1)
        tot += __shfl_xor_sync(0xffffffffu, tot, off);
    if ((tid & 31) == 0) wsum[tid >> 5] = tot;
    __syncthreads();
    float total = 0.0f;
    #pragma unroll
    for (int i = 0; i < 8; i++) total += wsum[i];
    float ginv = 1.0f / fmaxf(sqrtf(total), 1e-12f);

    float* od = out + (size_t)n * K_ * C_;
    for (int i = tid; i < K_ * C_; i += 256)
        od[i] = vsh[i] * ginv;
}

// ---------------------------------------------------------------------------
extern "C" void kernel_launch(void* const* d_in, const int* in_sizes, int n_in,
                              void* d_out, int out_size) {
    const float* x         = (const float*)d_in[0];
    const float* fc_w      = (const float*)d_in[1];
    const float* fc_b      = (const float*)d_in[2];
    const float* centroids = (const float*)d_in[3];
    float* out = (float*)d_out;

    cudaFuncSetAttribute(nv_main_kernel,
                         cudaFuncAttributeMaxDynamicSharedMemorySize,
                         SMEM_TOT);

    nv_main_kernel<<<NBLK, NTH, SMEM_TOT>>>(x, fc_w, fc_b);
    nv_reduce_kernel<<<(N_ * REDV + 255) / 256, 256>>>();
    nv_finalize_kernel<<<N_, 256>>>(centroids, out);
}

// round 8
// speedup vs baseline: 1.4342x; 1.0696x over previous
#include <cuda_runtime.h>
#include <cuda_bf16.h>
#include <math.h>
#include <stdint.h>

#define N_  16
#define C_  128
#define S_  16384
#define K_  64
#define TS  128
#define TILES 4
#define SGROUPS (S_ / (TS * TILES))   // 32
#define NBLK (N_ * SGROUPS)           // 512
#define NTH 512
#define LDX 136   // bf16 row stride x tiles [s][c] (col 128 = ||x|| hi/lo)
#define LDW 136
#define LDT 136
#define PSTRIDE 8256                  // 8192 vacc + 64 asum per block partial

__device__ float g_part[NBLK * PSTRIDE];
__device__ float g_red[N_ * PSTRIDE];

// ---------------------------------------------------------------------------
__device__ __forceinline__ uint32_t s2u(const void* p) {
    uint32_t a;
    asm("{ .reg .u64 t; cvta.to.shared.u64 t, %1; cvt.u32.u64 %0, t; }"
        : "=r"(a) : "l"(p));
    return a;
}
__device__ __forceinline__ void ldsm4(uint32_t* r, uint32_t addr) {
    asm volatile("ldmatrix.sync.aligned.m8n8.x4.shared.b16 {%0,%1,%2,%3}, [%4];"
                 : "=r"(r[0]), "=r"(r[1]), "=r"(r[2]), "=r"(r[3]) : "r"(addr));
}
__device__ __forceinline__ void ldsm2t(uint32_t& r0, uint32_t& r1, uint32_t addr) {
    asm volatile("ldmatrix.sync.aligned.m8n8.x2.trans.shared.b16 {%0,%1}, [%2];"
                 : "=r"(r0), "=r"(r1) : "r"(addr));
}
__device__ __forceinline__ void mma_bf16(float* d, const uint32_t* a,
                                         uint32_t b0, uint32_t b1) {
    asm volatile("mma.sync.aligned.m16n8k16.row.col.f32.bf16.bf16.f32 "
                 "{%0,%1,%2,%3}, {%4,%5,%6,%7}, {%8,%9}, {%0,%1,%2,%3};"
                 : "+f"(d[0]), "+f"(d[1]), "+f"(d[2]), "+f"(d[3])
                 : "r"(a[0]), "r"(a[1]), "r"(a[2]), "r"(a[3]), "r"(b0), "r"(b1));
}

// ---------------------------------------------------------------------------
// smem byte offsets
#define OFF_XH   0
#define OFF_XL   34816
#define OFF_WH   69632
#define OFF_WL   87040
#define OFF_SH   104448
#define OFF_SL   121856
#define OFF_BB   139264
#define OFF_PN   139520       // float[128][4]  (2048 B)
#define OFF_PS   141568       // float[128][2]  (1024 B)
#define SMEM_TOT 142592

__global__ __launch_bounds__(NTH, 1)
void nv_main_kernel(const float* __restrict__ x,
                    const float* __restrict__ fc_w,
                    const float* __restrict__ fc_b) {
    extern __shared__ char smem[];
    __nv_bfloat16* XH  = (__nv_bfloat16*)(smem + OFF_XH);
    __nv_bfloat16* XL  = (__nv_bfloat16*)(smem + OFF_XL);
    __nv_bfloat16* WH  = (__nv_bfloat16*)(smem + OFF_WH);
    __nv_bfloat16* WL  = (__nv_bfloat16*)(smem + OFF_WL);
    __nv_bfloat16* SHm = (__nv_bfloat16*)(smem + OFF_SH);
    __nv_bfloat16* SLm = (__nv_bfloat16*)(smem + OFF_SL);
    float* BB = (float*)(smem + OFF_BB);
    float* PN = (float*)(smem + OFF_PN);
    float* PS = (float*)(smem + OFF_PS);

    const uint32_t XHu = s2u(XH), XLu = s2u(XL), WHu = s2u(WH), WLu = s2u(WL);
    const uint32_t SHu = s2u(SHm), SLu = s2u(SLm);

    const int n   = blockIdx.x >> 5;
    const int g   = blockIdx.x & (SGROUPS - 1);
    const int tid = threadIdx.x;
    const int l   = tid & 31;
    const int w   = tid >> 5;            // 0..15
    const int sl  = tid & 127;           // position (load/convert)
    const int q   = tid >> 7;            // channel quarter 0..3

    // GEMM1 split: m-stripe (w&7), K-half kh (w>>3)
    const int m0g1 = (w & 7) * 16;
    const int kh   = w >> 3;
    // GEMM2 split: k-stripe (w&3), c-range (w>>2)*32
    const int m0b  = (w & 3) * 16;
    const int nb   = (w >> 2) * 32;

    // ---- load fc_w hi/lo + bias (once per block) ----
    for (int i = tid; i < K_ * C_; i += NTH) {
        int k = i >> 7, c = i & 127;
        float v = fc_w[i];
        __nv_bfloat16 hi = __float2bfloat16(v);
        WH[k * LDW + c] = hi;
        WL[k * LDW + c] = __float2bfloat16(v - __bfloat162float(hi));
    }
    if (tid < K_) BB[tid] = fc_b[tid];
    __syncthreads();

    const int cst = (l & 3) * 2;
    float bias_r[4][2];
    #pragma unroll
    for (int j = 0; j < 4; j++) {
        bias_r[j][0] = BB[kh * 32 + j * 8 + cst];
        bias_r[j][1] = BB[kh * 32 + j * 8 + cst + 1];
    }

    float vacc[4][4];
    #pragma unroll
    for (int j = 0; j < 4; j++)
        #pragma unroll
        for (int p = 0; p < 4; p++) vacc[j][p] = 0.0f;
    float vacc8[4] = {0.f, 0.f, 0.f, 0.f};   // norm-column (a_sum)

    #pragma unroll 1
    for (int t = 0; t < TILES; t++) {
        const int s0 = g * (TS * TILES) + t * TS;
        const float* xg = x + (size_t)n * C_ * S_ + s0;
        __syncthreads();                         // A: prev tile consumers done

        // ---- single pass: load raw x (32 ch/thread), hi/lo, ss partial ----
        float ss = 0.0f;
        #pragma unroll 8
        for (int c = q * 32; c < q * 32 + 32; c += 2) {
            float v0 = xg[(size_t)c * S_ + sl];
            float v1 = xg[(size_t)(c + 1) * S_ + sl];
            ss = fmaf(v0, v0, ss); ss = fmaf(v1, v1, ss);
            __nv_bfloat16 h0 = __float2bfloat16(v0);
            __nv_bfloat16 h1 = __float2bfloat16(v1);
            __nv_bfloat162 hp; hp.x = h0; hp.y = h1;
            __nv_bfloat162 lp;
            lp.x = __float2bfloat16(v0 - __bfloat162float(h0));
            lp.y = __float2bfloat16(v1 - __bfloat162float(h1));
            *(__nv_bfloat162*)&XH[sl * LDX + c] = hp;
            *(__nv_bfloat162*)&XL[sl * LDX + c] = lp;
        }
        PN[sl * 4 + q] = ss;
        __syncthreads();                         // S1: XH/XL + PN ready

        // norm column (c=128): ||x_s|| hi/lo, so soft' @ normcol = a_sum
        if (q == 0) {
            float s4 = PN[sl*4] + PN[sl*4+1] + PN[sl*4+2] + PN[sl*4+3];
            float nrm = fmaxf(sqrtf(s4), 1e-12f);
            __nv_bfloat16 h = __float2bfloat16(nrm);
            XH[sl * LDX + 128] = h;
            XL[sl * LDX + 128] = __float2bfloat16(nrm - __bfloat162float(h));
        }

        // ---- GEMM1 on RAW x: warp = m16 stripe x 32 clusters (K-half) ----
        float lacc[4][4];
        #pragma unroll
        for (int j = 0; j < 4; j++)
            #pragma unroll
            for (int p = 0; p < 4; p++) lacc[j][p] = 0.0f;
        {
            uint32_t aoffA = (uint32_t)(((m0g1 + (l & 15)) * LDX + ((l >> 4) << 3)) * 2);
            uint32_t boffB = (uint32_t)(((((l >> 4) << 3) + (l & 7) + kh * 32) * LDW
                                        + (((l >> 3) & 1) << 3)) * 2);
            #pragma unroll 1
            for (int kc = 0; kc < 8; kc++) {
                uint32_t axh[4], axl[4];
                ldsm4(axh, XHu + aoffA + kc * 32);
                ldsm4(axl, XLu + aoffA + kc * 32);
                #pragma unroll
                for (int j = 0; j < 2; j++) {
                    uint32_t bwh[4], bwl[4];
                    uint32_t bo = boffB + kc * 32 + j * 16 * LDW * 2;
                    ldsm4(bwh, WHu + bo);
                    ldsm4(bwl, WLu + bo);
                    mma_bf16(lacc[2*j],   axh, bwh[0], bwh[1]);
                    mma_bf16(lacc[2*j+1], axh, bwh[2], bwh[3]);
                    mma_bf16(lacc[2*j],   axl, bwh[0], bwh[1]);
                    mma_bf16(lacc[2*j+1], axl, bwh[2], bwh[3]);
                    mma_bf16(lacc[2*j],   axh, bwl[0], bwl[1]);
                    mma_bf16(lacc[2*j+1], axh, bwl[2], bwl[3]);
                }
            }
        }

        // ---- post-scale + softmax (no max-shift; logits bounded) ----
        {
            const int r0 = m0g1 + (l >> 2);
            float s40 = PN[r0*4] + PN[r0*4+1] + PN[r0*4+2] + PN[r0*4+3];
            float s41 = PN[(r0+8)*4] + PN[(r0+8)*4+1]
                      + PN[(r0+8)*4+2] + PN[(r0+8)*4+3];
            float sc0 = 1.0f / fmaxf(sqrtf(s40), 1e-12f);
            float sc1 = 1.0f / fmaxf(sqrtf(s41), 1e-12f);

            float se0 = 0.0f, se1 = 0.0f;
            #pragma unroll
            for (int j = 0; j < 4; j++) {
                float e;
                e = __expf(fmaf(lacc[j][0], sc0, bias_r[j][0])); lacc[j][0] = e; se0 += e;
                e = __expf(fmaf(lacc[j][1], sc0, bias_r[j][1])); lacc[j][1] = e; se0 += e;
                e = __expf(fmaf(lacc[j][2], sc1, bias_r[j][0])); lacc[j][2] = e; se1 += e;
                e = __expf(fmaf(lacc[j][3], sc1, bias_r[j][1])); lacc[j][3] = e; se1 += e;
            }
            se0 += __shfl_xor_sync(0xffffffffu, se0, 1);
            se0 += __shfl_xor_sync(0xffffffffu, se0, 2);
            se1 += __shfl_xor_sync(0xffffffffu, se1, 1);
            se1 += __shfl_xor_sync(0xffffffffu, se1, 2);
            if ((l & 3) == 0) {
                PS[r0 * 2 + kh]       = se0;
                PS[(r0 + 8) * 2 + kh] = se1;
            }
            __syncthreads();                     // Ssum: half-sums exchanged

            float inv0 = sc0 / (PS[r0 * 2] + PS[r0 * 2 + 1]);
            float inv1 = sc1 / (PS[(r0 + 8) * 2] + PS[(r0 + 8) * 2 + 1]);

            #pragma unroll
            for (int j = 0; j < 4; j++) {
                int k0 = kh * 32 + j * 8 + cst;
                float v00 = lacc[j][0] * inv0, v01 = lacc[j][1] * inv0;
                float v10 = lacc[j][2] * inv1, v11 = lacc[j][3] * inv1;
                __nv_bfloat16 h;
                h = __float2bfloat16(v00);
                SHm[k0 * LDT + r0] = h;
                SLm[k0 * LDT + r0] = __float2bfloat16(v00 - __bfloat162float(h));
                h = __float2bfloat16(v01);
                SHm[(k0 + 1) * LDT + r0] = h;
                SLm[(k0 + 1) * LDT + r0] = __float2bfloat16(v01 - __bfloat162float(h));
                h = __float2bfloat16(v10);
                SHm[k0 * LDT + r0 + 8] = h;
                SLm[k0 * LDT + r0 + 8] = __float2bfloat16(v10 - __bfloat162float(h));
                h = __float2bfloat16(v11);
                SHm[(k0 + 1) * LDT + r0 + 8] = h;
                SLm[(k0 + 1) * LDT + r0 + 8] = __float2bfloat16(v11 - __bfloat162float(h));
            }
        }
        __syncthreads();                         // S2: soft' + norm col ready

        // ---- GEMM2: warp = k16 stripe x c32 range, 3-term ----
        #pragma unroll 1
        for (int ks = 0; ks < 8; ks++) {
            int sb = ks * 16;
            uint32_t aoff = (uint32_t)(((m0b + (l & 15)) * LDT + sb
                                       + ((l >> 4) << 3)) * 2);
            uint32_t ash[4], asl[4];
            ldsm4(ash, SHu + aoff);
            ldsm4(asl, SLu + aoff);
            uint32_t boff = (uint32_t)(((sb + (l & 15)) * LDX) * 2);
            #pragma unroll
            for (int j = 0; j < 4; j++) {
                int n0 = nb + j * 8;
                uint32_t bxh0, bxh1, bxl0, bxl1;
                ldsm2t(bxh0, bxh1, XHu + boff + n0 * 2);
                ldsm2t(bxl0, bxl1, XLu + boff + n0 * 2);
                mma_bf16(vacc[j], ash, bxh0, bxh1);
                mma_bf16(vacc[j], asl, bxh0, bxh1);
                mma_bf16(vacc[j], ash, bxl0, bxl1);
            }
            if (nb == 96) {   // norm column at c=128 -> a_sum
                uint32_t bxh0, bxh1, bxl0, bxl1;
                ldsm2t(bxh0, bxh1, XHu + boff + 128 * 2);
                ldsm2t(bxl0, bxl1, XLu + boff + 128 * 2);
                mma_bf16(vacc8, ash, bxh0, bxh1);
                mma_bf16(vacc8, asl, bxh0, bxh1);
                mma_bf16(vacc8, ash, bxl0, bxl1);
            }
        }
    }

    // ---- write per-block partial (no atomics) ----
    float* vdst = g_part + (size_t)blockIdx.x * PSTRIDE;
    {
        int r0 = m0b + (l >> 2);
        #pragma unroll
        for (int j = 0; j < 4; j++) {
            int c = nb + j * 8 + cst;
            vdst[r0 * C_ + c]           = vacc[j][0];
            vdst[r0 * C_ + c + 1]       = vacc[j][1];
            vdst[(r0 + 8) * C_ + c]     = vacc[j][2];
            vdst[(r0 + 8) * C_ + c + 1] = vacc[j][3];
        }
        if (nb == 96 && (l & 3) == 0) {
            vdst[8192 + r0]     = vacc8[0];
            vdst[8192 + r0 + 8] = vacc8[2];
        }
    }
}

// ---------------------------------------------------------------------------
// Wide parallel reduction: 512 partials -> 16.
#define REDV (PSTRIDE / 4)            // 2064 float4 per n
__global__ __launch_bounds__(256)
void nv_reduce_kernel() {
    int idx = blockIdx.x * 256 + threadIdx.x;
    if (idx >= N_ * REDV) return;
    int n  = idx / REDV;
    int e4 = idx - n * REDV;
    const float4* pb = (const float4*)(g_part + (size_t)n * SGROUPS * PSTRIDE)
                       + e4;
    float4 s = make_float4(0.f, 0.f, 0.f, 0.f);
    #pragma unroll 8
    for (int p = 0; p < SGROUPS; p++) {
        float4 v = pb[(size_t)p * (PSTRIDE / 4)];
        s.x += v.x; s.y += v.y; s.z += v.z; s.w += v.w;
    }
    ((float4*)(g_red + (size_t)n * PSTRIDE))[e4] = s;
}

// ---------------------------------------------------------------------------
__global__ __launch_bounds__(256)
void nv_finalize_kernel(const float* __restrict__ centroids,
                        float* __restrict__ out) {
    __shared__ float vsh[K_ * C_];
    __shared__ float ash[K_];
    __shared__ float wsum[8];

    const int n   = blockIdx.x;
    const int tid = threadIdx.x;
    const float* rb = g_red + (size_t)n * PSTRIDE;

    for (int e = tid * 4; e < K_ * C_; e += 256 * 4)
        *(float4*)&vsh[e] = *(const float4*)&rb[e];
    if (tid < K_) ash[tid] = rb[8192 + tid];
    __syncthreads();

    const int k  = tid >> 2;
    const int cb = (tid & 3) * 32;
    const float ak = ash[k];

    float ssk = 0.0f;
    #pragma unroll 8
    for (int c = 0; c < 32; c++) {
        int idx = k * C_ + cb + c;
        float v = vsh[idx] - ak * centroids[idx];
        vsh[idx] = v;
        ssk = fmaf(v, v, ssk);
    }
    ssk += __shfl_xor_sync(0xffffffffu, ssk, 1);
    ssk += __shfl_xor_sync(0xffffffffu, ssk, 2);
    float rinv = 1.0f / fmaxf(sqrtf(ssk), 1e-12f);

    float tot = 0.0f;
    #pragma unroll 8
    for (int c = 0; c < 32; c++) {
        int idx = k * C_ + cb + c;
        float tv = vsh[idx] * rinv;
        vsh[idx] = tv;
        tot = fmaf(tv, tv, tot);
    }
    #pragma unroll
    for (int off = 16; off > 0; off >>= 1)
        tot += __shfl_xor_sync(0xffffffffu, tot, off);
    if ((tid & 31) == 0) wsum[tid >> 5] = tot;
    __syncthreads();
    float total = 0.0f;
    #pragma unroll
    for (int i = 0; i < 8; i++) total += wsum[i];
    float ginv = 1.0f / fmaxf(sqrtf(total), 1e-12f);

    float* od = out + (size_t)n * K_ * C_;
    for (int i = tid; i < K_ * C_; i += 256)
        od[i] = vsh[i] * ginv;
}

// ---------------------------------------------------------------------------
extern "C" void kernel_launch(void* const* d_in, const int* in_sizes, int n_in,
                              void* d_out, int out_size) {
    const float* x         = (const float*)d_in[0];
    const float* fc_w      = (const float*)d_in[1];
    const float* fc_b      = (const float*)d_in[2];
    const float* centroids = (const float*)d_in[3];
    float* out = (float*)d_out;

    cudaFuncSetAttribute(nv_main_kernel,
                         cudaFuncAttributeMaxDynamicSharedMemorySize,
                         SMEM_TOT);

    nv_main_kernel<<<NBLK, NTH, SMEM_TOT>>>(x, fc_w, fc_b);
    nv_reduce_kernel<<<(N_ * REDV + 255) / 256, 256>>>();
    nv_finalize_kernel<<<N_, 256>>>(centroids, out);
}

// round 9
// speedup vs baseline: 1.7196x; 1.1990x over previous
#include <cuda_runtime.h>
#include <cuda_bf16.h>
#include <math.h>
#include <stdint.h>

#define N_  16
#define C_  128
#define S_  16384
#define K_  64
#define TS  64
#define TILES 8
#define SGROUPS (S_ / (TS * TILES))   // 32
#define NBLK (N_ * SGROUPS)           // 512
#define NTH 256
#define LDX 136   // bf16 row stride x tiles [s][c] (col 128 = ||x|| hi/lo)
#define LDW 136
#define LDT2 72   // bf16 row stride softT [k][s], s=64 + pad
#define PSTRIDE 8256                  // 8192 vacc + 64 asum per block partial

__device__ float g_part[NBLK * PSTRIDE];
__device__ float g_red[N_ * PSTRIDE];

// ---------------------------------------------------------------------------
__device__ __forceinline__ uint32_t s2u(const void* p) {
    uint32_t a;
    asm("{ .reg .u64 t; cvta.to.shared.u64 t, %1; cvt.u32.u64 %0, t; }"
        : "=r"(a) : "l"(p));
    return a;
}
__device__ __forceinline__ void ldsm4(uint32_t* r, uint32_t addr) {
    asm volatile("ldmatrix.sync.aligned.m8n8.x4.shared.b16 {%0,%1,%2,%3}, [%4];"
                 : "=r"(r[0]), "=r"(r[1]), "=r"(r[2]), "=r"(r[3]) : "r"(addr));
}
__device__ __forceinline__ void ldsm2t(uint32_t& r0, uint32_t& r1, uint32_t addr) {
    asm volatile("ldmatrix.sync.aligned.m8n8.x2.trans.shared.b16 {%0,%1}, [%2];"
                 : "=r"(r0), "=r"(r1) : "r"(addr));
}
__device__ __forceinline__ void mma_bf16(float* d, const uint32_t* a,
                                         uint32_t b0, uint32_t b1) {
    asm volatile("mma.sync.aligned.m16n8k16.row.col.f32.bf16.bf16.f32 "
                 "{%0,%1,%2,%3}, {%4,%5,%6,%7}, {%8,%9}, {%0,%1,%2,%3};"
                 : "+f"(d[0]), "+f"(d[1]), "+f"(d[2]), "+f"(d[3])
                 : "r"(a[0]), "r"(a[1]), "r"(a[2]), "r"(a[3]), "r"(b0), "r"(b1));
}

// ---------------------------------------------------------------------------
// smem byte offsets (ldsm bases 1024-aligned)
#define OFF_XH   0
#define OFF_XL   17408
#define OFF_WH   34816
#define OFF_WL   52224
#define OFF_SH   69632
#define OFF_SL   78848
#define OFF_BB   88064
#define OFF_PN   88320        // float[64][4]
#define OFF_PS   89344        // float[64][2]
#define SMEM_TOT 89856

__global__ __launch_bounds__(NTH, 2)
void nv_main_kernel(const float* __restrict__ x,
                    const float* __restrict__ fc_w,
                    const float* __restrict__ fc_b) {
    extern __shared__ char smem[];
    __nv_bfloat16* XH  = (__nv_bfloat16*)(smem + OFF_XH);
    __nv_bfloat16* XL  = (__nv_bfloat16*)(smem + OFF_XL);
    __nv_bfloat16* WH  = (__nv_bfloat16*)(smem + OFF_WH);
    __nv_bfloat16* WL  = (__nv_bfloat16*)(smem + OFF_WL);
    __nv_bfloat16* SHm = (__nv_bfloat16*)(smem + OFF_SH);
    __nv_bfloat16* SLm = (__nv_bfloat16*)(smem + OFF_SL);
    float* BB = (float*)(smem + OFF_BB);
    float* PN = (float*)(smem + OFF_PN);
    float* PS = (float*)(smem + OFF_PS);

    const uint32_t XHu = s2u(XH), XLu = s2u(XL), WHu = s2u(WH), WLu = s2u(WL);
    const uint32_t SHu = s2u(SHm), SLu = s2u(SLm);

    const int n   = blockIdx.x >> 5;
    const int g   = blockIdx.x & (SGROUPS - 1);
    const int tid = threadIdx.x;
    const int l   = tid & 31;
    const int w   = tid >> 5;            // 0..7
    const int sl  = tid & 63;            // position (load/convert)
    const int q   = tid >> 6;            // channel quarter 0..3

    // GEMM1 split: m-stripe (w&3), K-half kh (w>>2)
    const int m0g1 = (w & 3) * 16;
    const int kh   = w >> 2;
    // GEMM2 split: k-stripe (w&3), c-half (w>>2)*64
    const int m0b  = (w & 3) * 16;
    const int nb   = (w >> 2) * 64;

    // ---- load fc_w hi/lo + bias (once per block) ----
    for (int i = tid; i < K_ * C_; i += NTH) {
        int k = i >> 7, c = i & 127;
        float v = fc_w[i];
        __nv_bfloat16 hi = __float2bfloat16(v);
        WH[k * LDW + c] = hi;
        WL[k * LDW + c] = __float2bfloat16(v - __bfloat162float(hi));
    }
    if (tid < K_) BB[tid] = fc_b[tid];
    __syncthreads();

    const int cst = (l & 3) * 2;
    float bias_r[4][2];
    #pragma unroll
    for (int j = 0; j < 4; j++) {
        bias_r[j][0] = BB[kh * 32 + j * 8 + cst];
        bias_r[j][1] = BB[kh * 32 + j * 8 + cst + 1];
    }

    float vacc[8][4];
    #pragma unroll
    for (int j = 0; j < 8; j++)
        #pragma unroll
        for (int p = 0; p < 4; p++) vacc[j][p] = 0.0f;
    float vacc8[4] = {0.f, 0.f, 0.f, 0.f};   // norm-column (a_sum)

    #pragma unroll 1
    for (int t = 0; t < TILES; t++) {
        const int s0 = g * (TS * TILES) + t * TS;
        const float* xg = x + (size_t)n * C_ * S_ + s0;
        __syncthreads();                         // A: prev tile consumers done

        // ---- single pass: load raw x (32 ch/thread), hi/lo, ss partial ----
        float ss = 0.0f;
        #pragma unroll 8
        for (int c = q * 32; c < q * 32 + 32; c += 2) {
            float v0 = xg[(size_t)c * S_ + sl];
            float v1 = xg[(size_t)(c + 1) * S_ + sl];
            ss = fmaf(v0, v0, ss); ss = fmaf(v1, v1, ss);
            __nv_bfloat16 h0 = __float2bfloat16(v0);
            __nv_bfloat16 h1 = __float2bfloat16(v1);
            __nv_bfloat162 hp; hp.x = h0; hp.y = h1;
            __nv_bfloat162 lp;
            lp.x = __float2bfloat16(v0 - __bfloat162float(h0));
            lp.y = __float2bfloat16(v1 - __bfloat162float(h1));
            *(__nv_bfloat162*)&XH[sl * LDX + c] = hp;
            *(__nv_bfloat162*)&XL[sl * LDX + c] = lp;
        }
        PN[sl * 4 + q] = ss;
        __syncthreads();                         // S1: XH/XL + PN ready

        // norm column (c=128): ||x_s|| hi/lo, so soft' @ normcol = a_sum
        if (q == 0) {
            float s4 = PN[sl*4] + PN[sl*4+1] + PN[sl*4+2] + PN[sl*4+3];
            float nrm = fmaxf(sqrtf(s4), 1e-12f);
            __nv_bfloat16 h = __float2bfloat16(nrm);
            XH[sl * LDX + 128] = h;
            XL[sl * LDX + 128] = __float2bfloat16(nrm - __bfloat162float(h));
        }

        // ---- GEMM1 on RAW x: warp = m16 stripe x 32 clusters (K-half) ----
        float lacc[4][4];
        #pragma unroll
        for (int j = 0; j < 4; j++)
            #pragma unroll
            for (int p = 0; p < 4; p++) lacc[j][p] = 0.0f;
        {
            uint32_t aoffA = (uint32_t)(((m0g1 + (l & 15)) * LDX + ((l >> 4) << 3)) * 2);
            uint32_t boffB = (uint32_t)(((((l >> 4) << 3) + (l & 7) + kh * 32) * LDW
                                        + (((l >> 3) & 1) << 3)) * 2);
            #pragma unroll 1
            for (int kc = 0; kc < 8; kc++) {
                uint32_t axh[4], axl[4];
                ldsm4(axh, XHu + aoffA + kc * 32);
                ldsm4(axl, XLu + aoffA + kc * 32);
                #pragma unroll
                for (int j = 0; j < 2; j++) {
                    uint32_t bwh[4], bwl[4];
                    uint32_t bo = boffB + kc * 32 + j * 16 * LDW * 2;
                    ldsm4(bwh, WHu + bo);
                    ldsm4(bwl, WLu + bo);
                    mma_bf16(lacc[2*j],   axh, bwh[0], bwh[1]);
                    mma_bf16(lacc[2*j+1], axh, bwh[2], bwh[3]);
                    mma_bf16(lacc[2*j],   axl, bwh[0], bwh[1]);
                    mma_bf16(lacc[2*j+1], axl, bwh[2], bwh[3]);
                    mma_bf16(lacc[2*j],   axh, bwl[0], bwl[1]);
                    mma_bf16(lacc[2*j+1], axh, bwl[2], bwl[3]);
                }
            }
        }

        // ---- post-scale + softmax (no max-shift; logits bounded) ----
        {
            const int r0 = m0g1 + (l >> 2);
            float s40 = PN[r0*4] + PN[r0*4+1] + PN[r0*4+2] + PN[r0*4+3];
            float s41 = PN[(r0+8)*4] + PN[(r0+8)*4+1]
                      + PN[(r0+8)*4+2] + PN[(r0+8)*4+3];
            float sc0 = 1.0f / fmaxf(sqrtf(s40), 1e-12f);
            float sc1 = 1.0f / fmaxf(sqrtf(s41), 1e-12f);

            float se0 = 0.0f, se1 = 0.0f;
            #pragma unroll
            for (int j = 0; j < 4; j++) {
                float e;
                e = __expf(fmaf(lacc[j][0], sc0, bias_r[j][0])); lacc[j][0] = e; se0 += e;
                e = __expf(fmaf(lacc[j][1], sc0, bias_r[j][1])); lacc[j][1] = e; se0 += e;
                e = __expf(fmaf(lacc[j][2], sc1, bias_r[j][0])); lacc[j][2] = e; se1 += e;
                e = __expf(fmaf(lacc[j][3], sc1, bias_r[j][1])); lacc[j][3] = e; se1 += e;
            }
            se0 += __shfl_xor_sync(0xffffffffu, se0, 1);
            se0 += __shfl_xor_sync(0xffffffffu, se0, 2);
            se1 += __shfl_xor_sync(0xffffffffu, se1, 1);
            se1 += __shfl_xor_sync(0xffffffffu, se1, 2);
            if ((l & 3) == 0) {
                PS[r0 * 2 + kh]       = se0;
                PS[(r0 + 8) * 2 + kh] = se1;
            }
            __syncthreads();                     // Ssum: half-sums exchanged

            float inv0 = sc0 / (PS[r0 * 2] + PS[r0 * 2 + 1]);
            float inv1 = sc1 / (PS[(r0 + 8) * 2] + PS[(r0 + 8) * 2 + 1]);

            #pragma unroll
            for (int j = 0; j < 4; j++) {
                int k0 = kh * 32 + j * 8 + cst;
                float v00 = lacc[j][0] * inv0, v01 = lacc[j][1] * inv0;
                float v10 = lacc[j][2] * inv1, v11 = lacc[j][3] * inv1;
                __nv_bfloat16 h;
                h = __float2bfloat16(v00);
                SHm[k0 * LDT2 + r0] = h;
                SLm[k0 * LDT2 + r0] = __float2bfloat16(v00 - __bfloat162float(h));
                h = __float2bfloat16(v01);
                SHm[(k0 + 1) * LDT2 + r0] = h;
                SLm[(k0 + 1) * LDT2 + r0] = __float2bfloat16(v01 - __bfloat162float(h));
                h = __float2bfloat16(v10);
                SHm[k0 * LDT2 + r0 + 8] = h;
                SLm[k0 * LDT2 + r0 + 8] = __float2bfloat16(v10 - __bfloat162float(h));
                h = __float2bfloat16(v11);
                SHm[(k0 + 1) * LDT2 + r0 + 8] = h;
                SLm[(k0 + 1) * LDT2 + r0 + 8] = __float2bfloat16(v11 - __bfloat162float(h));
            }
        }
        __syncthreads();                         // S2: soft' + norm col ready

        // ---- GEMM2: warp = k16 stripe x c64 half, 3-term ----
        #pragma unroll 1
        for (int ks = 0; ks < 4; ks++) {
            int sb = ks * 16;
            uint32_t aoff = (uint32_t)(((m0b + (l & 15)) * LDT2 + sb
                                       + ((l >> 4) << 3)) * 2);
            uint32_t ash[4], asl[4];
            ldsm4(ash, SHu + aoff);
            ldsm4(asl, SLu + aoff);
            uint32_t boff = (uint32_t)(((sb + (l & 15)) * LDX) * 2);
            #pragma unroll
            for (int j = 0; j < 8; j++) {
                int n0 = nb + j * 8;
                uint32_t bxh0, bxh1, bxl0, bxl1;
                ldsm2t(bxh0, bxh1, XHu + boff + n0 * 2);
                ldsm2t(bxl0, bxl1, XLu + boff + n0 * 2);
                mma_bf16(vacc[j], ash, bxh0, bxh1);
                mma_bf16(vacc[j], asl, bxh0, bxh1);
                mma_bf16(vacc[j], ash, bxl0, bxl1);
            }
            if (nb == 64) {   // norm column at c=128 -> a_sum
                uint32_t bxh0, bxh1, bxl0, bxl1;
                ldsm2t(bxh0, bxh1, XHu + boff + 128 * 2);
                ldsm2t(bxl0, bxl1, XLu + boff + 128 * 2);
                mma_bf16(vacc8, ash, bxh0, bxh1);
                mma_bf16(vacc8, asl, bxh0, bxh1);
                mma_bf16(vacc8, ash, bxl0, bxl1);
            }
        }
    }

    // ---- write per-block partial (no atomics) ----
    float* vdst = g_part + (size_t)blockIdx.x * PSTRIDE;
    {
        int r0 = m0b + (l >> 2);
        #pragma unroll
        for (int j = 0; j < 8; j++) {
            int c = nb + j * 8 + cst;
            vdst[r0 * C_ + c]           = vacc[j][0];
            vdst[r0 * C_ + c + 1]       = vacc[j][1];
            vdst[(r0 + 8) * C_ + c]     = vacc[j][2];
            vdst[(r0 + 8) * C_ + c + 1] = vacc[j][3];
        }
        if (nb == 64 && (l & 3) == 0) {
            vdst[8192 + r0]     = vacc8[0];
            vdst[8192 + r0 + 8] = vacc8[2];
        }
    }
}

// ---------------------------------------------------------------------------
// Wide parallel reduction: 512 partials -> 16.
#define REDV (PSTRIDE / 4)            // 2064 float4 per n
__global__ __launch_bounds__(256)
void nv_reduce_kernel() {
    int idx = blockIdx.x * 256 + threadIdx.x;
    if (idx >= N_ * REDV) return;
    int n  = idx / REDV;
    int e4 = idx - n * REDV;
    const float4* pb = (const float4*)(g_part + (size_t)n * SGROUPS * PSTRIDE)
                       + e4;
    float4 s = make_float4(0.f, 0.f, 0.f, 0.f);
    #pragma unroll 8
    for (int p = 0; p < SGROUPS; p++) {
        float4 v = pb[(size_t)p * (PSTRIDE / 4)];
        s.x += v.x; s.y += v.y; s.z += v.z; s.w += v.w;
    }
    ((float4*)(g_red + (size_t)n * PSTRIDE))[e4] = s;
}

// ---------------------------------------------------------------------------
__global__ __launch_bounds__(256)
void nv_finalize_kernel(const float* __restrict__ centroids,
                        float* __restrict__ out) {
    __shared__ float vsh[K_ * C_];
    __shared__ float ash[K_];
    __shared__ float wsum[8];

    const int n   = blockIdx.x;
    const int tid = threadIdx.x;
    const float* rb = g_red + (size_t)n * PSTRIDE;

    for (int e = tid * 4; e < K_ * C_; e += 256 * 4)
        *(float4*)&vsh[e] = *(const float4*)&rb[e];
    if (tid < K_) ash[tid] = rb[8192 + tid];
    __syncthreads();

    const int k  = tid >> 2;
    const int cb = (tid & 3) * 32;
    const float ak = ash[k];

    float ssk = 0.0f;
    #pragma unroll 8
    for (int c = 0; c < 32; c++) {
        int idx = k * C_ + cb + c;
        float v = vsh[idx] - ak * centroids[idx];
        vsh[idx] = v;
        ssk = fmaf(v, v, ssk);
    }
    ssk += __shfl_xor_sync(0xffffffffu, ssk, 1);
    ssk += __shfl_xor_sync(0xffffffffu, ssk, 2);
    float rinv = 1.0f / fmaxf(sqrtf(ssk), 1e-12f);

    float tot = 0.0f;
    #pragma unroll 8
    for (int c = 0; c < 32; c++) {
        int idx = k * C_ + cb + c;
        float tv = vsh[idx] * rinv;
        vsh[idx] = tv;
        tot = fmaf(tv, tv, tot);
    }
    #pragma unroll
    for (int off = 16; off > 0; off >>= 1)
        tot += __shfl_xor_sync(0xffffffffu, tot, off);
    if ((tid & 31) == 0) wsum[tid >> 5] = tot;
    __syncthreads();
    float total = 0.0f;
    #pragma unroll
    for (int i = 0; i < 8; i++) total += wsum[i];
    float ginv = 1.0f / fmaxf(sqrtf(total), 1e-12f);

    float* od = out + (size_t)n * K_ * C_;
    for (int i = tid; i < K_ * C_; i += 256)
        od[i] = vsh[i] * ginv;
}

// ---------------------------------------------------------------------------
extern "C" void kernel_launch(void* const* d_in, const int* in_sizes, int n_in,
                              void* d_out, int out_size) {
    const float* x         = (const float*)d_in[0];
    const float* fc_w      = (const float*)d_in[1];
    const float* fc_b      = (const float*)d_in[2];
    const float* centroids = (const float*)d_in[3];
    float* out = (float*)d_out;

    cudaFuncSetAttribute(nv_main_kernel,
                         cudaFuncAttributeMaxDynamicSharedMemorySize,
                         SMEM_TOT);

    nv_main_kernel<<<NBLK, NTH, SMEM_TOT>>>(x, fc_w, fc_b);
    nv_reduce_kernel<<<(N_ * REDV + 255) / 256, 256>>>();
    nv_finalize_kernel<<<N_, 256>>>(centroids, out);
}